// round 12
// baseline (speedup 1.0000x reference)
#include <cuda_runtime.h>
#include <cuda_fp16.h>
#include <math.h>
#include <stdint.h>

#define T_TOK 4096
#define D_DIM 1024
#define F_DIM 4096
#define N_EXP 8
#define TOTAL_ROWS (T_TOK * 2)

#define BM 64
#define BN 128
#define BK 32

// smem: A plane 64 rows, B plane 128 rows, 80B row stride (64B data + 16B pad)
#define ROWB 80
#define APL 0
#define BPL (64 * ROWB)             // 5120
#define STAGE (192 * ROWB)          // 15360
#define NBUF 4
#define DSMEM (NBUF * STAGE)        // 61440  (3 CTAs = 184320B <= 228KB)

// ---- scratch (device globals: no allocations allowed) ----
__device__ __half g_Hh[(size_t)TOTAL_ROWS * F_DIM];
__device__ __half g_W1h[(size_t)N_EXP * F_DIM * D_DIM];
__device__ __half g_W2h[(size_t)N_EXP * D_DIM * F_DIM];
__device__ __half g_xh[(size_t)T_TOK * D_DIM];
__device__ int   g_rowmap[TOTAL_ROWS];
__device__ float g_roww[TOTAL_ROWS];
__device__ int   g_counts[N_EXP];
__device__ int   g_offsets[N_EXP];
__device__ int   g_tope[T_TOK * 2];
__device__ float g_topw[T_TOK * 2];

// ---------------- PTX helpers ----------------
__device__ __forceinline__ uint32_t smem_u32(const void* p) {
    uint32_t a;
    asm("{ .reg .u64 t; cvta.to.shared.u64 t, %1; cvt.u32.u64 %0, t; }" : "=r"(a) : "l"(p));
    return a;
}
__device__ __forceinline__ void cp16(uint32_t dst, const void* src) {
    asm volatile("cp.async.cg.shared.global [%0], [%1], 16;" :: "r"(dst), "l"(src));
}
#define CP_COMMIT() asm volatile("cp.async.commit_group;" ::: "memory")
#define CP_WAIT(n)  asm volatile("cp.async.wait_group %0;" :: "n"(n) : "memory")
__device__ __forceinline__ void ldsm4(uint32_t& r0, uint32_t& r1, uint32_t& r2, uint32_t& r3,
                                      uint32_t a) {
    asm volatile("ldmatrix.sync.aligned.m8n8.x4.shared.b16 {%0,%1,%2,%3}, [%4];"
                 : "=r"(r0), "=r"(r1), "=r"(r2), "=r"(r3) : "r"(a));
}
__device__ __forceinline__ void mma16816(float* c, uint32_t a0, uint32_t a1,
                                         uint32_t a2, uint32_t a3,
                                         uint32_t b0, uint32_t b1) {
    asm volatile("mma.sync.aligned.m16n8k16.row.col.f32.f16.f16.f32 "
                 "{%0,%1,%2,%3}, {%4,%5,%6,%7}, {%8,%9}, {%0,%1,%2,%3};"
                 : "+f"(c[0]), "+f"(c[1]), "+f"(c[2]), "+f"(c[3])
                 : "r"(a0), "r"(a1), "r"(a2), "r"(a3), "r"(b0), "r"(b1));
}

// compute one BK=32 stage via ldmatrix. warp tile 32x32: acc[2][4][4]
__device__ __forceinline__ void compute_stage(uint32_t bufb, uint32_t aOff,
                                              uint32_t bOff0, uint32_t bOff1,
                                              float acc[2][4][4]) {
#pragma unroll
    for (int ks = 0; ks < 2; ks++) {
        uint32_t kb = ks * 32;
        uint32_t b0[4], b1[4];
        ldsm4(b0[0], b1[0], b0[1], b1[1], bufb + BPL + bOff0 + kb);
        ldsm4(b0[2], b1[2], b0[3], b1[3], bufb + BPL + bOff1 + kb);
#pragma unroll
        for (int mi = 0; mi < 2; mi++) {
            uint32_t a0, a1, a2, a3;
            ldsm4(a0, a1, a2, a3, bufb + APL + aOff + mi * (16 * ROWB) + kb);
#pragma unroll
            for (int nj = 0; nj < 4; nj++)
                mma16816(acc[mi][nj], a0, a1, a2, a3, b0[nj], b1[nj]);
        }
    }
}

// ---------------------------------------------------------------------------
// launch 0: fp32->fp16 converts for x|W1|W2, plus zero(out) and counts reset
#define X_B4   ((size_t)(T_TOK * D_DIM / 4))          // 1048576 == out float4 count
#define W_B4   ((size_t)N_EXP * F_DIM * D_DIM / 4)    // 8388608
__global__ void f2h_zero_kernel(const float* __restrict__ x,
                                const float* __restrict__ W1,
                                const float* __restrict__ W2,
                                float* __restrict__ out) {
    size_t i = (size_t)blockIdx.x * blockDim.x + threadIdx.x;
    if (i < X_B4) ((float4*)out)[i] = make_float4(0.f, 0.f, 0.f, 0.f);
    if (i < 8) g_counts[i] = 0;
    const float* s;
    __half* d;
    size_t j = i;
    if (j < X_B4) { s = x; d = g_xh; }
    else if (j < X_B4 + W_B4) { s = W1; d = g_W1h; j -= X_B4; }
    else { s = W2; d = g_W2h; j -= X_B4 + W_B4; }
    float4 v = ((const float4*)s)[j];
    __half2* dp = (__half2*)d;
    dp[2 * j] = __floats2half2_rn(v.x, v.y);
    dp[2 * j + 1] = __floats2half2_rn(v.z, v.w);
}

// launch 1: router
__global__ void router_kernel(const float* __restrict__ x, const float* __restrict__ Wr) {
    int gtid = blockIdx.x * blockDim.x + threadIdx.x;
    int t = gtid >> 5, lane = gtid & 31;
    if (t >= T_TOK) return;
    const float* xr = x + (size_t)t * D_DIM;
    float xv[32];
#pragma unroll
    for (int i = 0; i < 32; i++) xv[i] = xr[lane + i * 32];
    float logit[N_EXP];
#pragma unroll
    for (int e = 0; e < N_EXP; e++) {
        const float* w = Wr + (size_t)e * D_DIM;
        float s = 0.f;
#pragma unroll
        for (int i = 0; i < 32; i++) s += xv[i] * w[lane + i * 32];
#pragma unroll
        for (int o = 16; o > 0; o >>= 1) s += __shfl_xor_sync(0xffffffffu, s, o);
        logit[e] = s;
    }
    if (lane == 0) {
        int i0 = 0; float m0v = logit[0];
#pragma unroll
        for (int e = 1; e < N_EXP; e++) if (logit[e] > m0v) { m0v = logit[e]; i0 = e; }
        int i1 = -1; float m1v = -3.0e38f;
#pragma unroll
        for (int e = 0; e < N_EXP; e++) if (e != i0 && logit[e] > m1v) { m1v = logit[e]; i1 = e; }
        float e1 = expf(m1v - m0v);
        float w0 = 1.f / (1.f + e1);
        float w1 = e1 * w0;
        g_tope[2 * t] = i0;     g_topw[2 * t] = w0;
        g_tope[2 * t + 1] = i1; g_topw[2 * t + 1] = w1;
        atomicAdd(&g_counts[i0], 1);
        atomicAdd(&g_counts[i1], 1);
    }
}

// launch 2: scan + fill merged (single block)
__global__ void scanfill_kernel() {
    __shared__ int scur[N_EXP];
    int tid = threadIdx.x;
    if (tid == 0) {
        int o = 0;
        for (int e = 0; e < N_EXP; e++) { g_offsets[e] = o; scur[e] = o; o += g_counts[e]; }
    }
    __syncthreads();
    for (int t = tid; t < T_TOK; t += 256) {
#pragma unroll
        for (int k = 0; k < 2; k++) {
            int e = g_tope[2 * t + k];
            int pos = atomicAdd(&scur[e], 1);
            g_rowmap[pos] = t;
            g_roww[pos] = g_topw[2 * t + k];
        }
    }
}

// ---------------------------------------------------------------------------
// launch 3: GEMM1: H = gelu( gather(xh) @ W1h^T + b1 )
// 64x128 CTA tile, 8 warps of 32x32, cp.async 4-buf, ldmatrix; 3 CTAs/SM
// ---------------------------------------------------------------------------
__global__ __launch_bounds__(256, 3) void gemm1_mma(const float* __restrict__ b1) {
    int e = blockIdx.z;
    int rows = g_counts[e];
    int m0 = blockIdx.y * BM;
    if (m0 >= rows) return;
    int base = g_offsets[e];
    int n0 = blockIdx.x * BN;

    extern __shared__ char smem[];
    uint32_t sbase = smem_u32(smem);
    int tid = threadIdx.x;
    int wid = tid >> 5, lane = tid & 31;
    int wm = wid & 1, wn = wid >> 1;          // warp tile: M 32 x N 32
    int g = lane >> 2, q2 = lane & 3;

    // producers: threads 0-63 -> A rows, 64-191 -> B rows, 192-255 idle
    bool prod = tid < 192;
    const __half* gp = 0;
    uint32_t sdst = 0;
    if (tid < 64) {
        int ar = m0 + tid; if (ar >= rows) ar = rows - 1;
        gp = g_xh + (size_t)g_rowmap[base + ar] * D_DIM;
        sdst = sbase + APL + tid * ROWB;
    } else if (tid < 192) {
        int br = tid - 64;
        gp = g_W1h + ((size_t)e * F_DIM + n0 + br) * D_DIM;
        sdst = sbase + BPL + br * ROWB;
    }

    int sel = lane >> 3;
    uint32_t aOff = (uint32_t)((wm * 32 + (lane & 15)) * ROWB + (lane >> 4) * 16);
    uint32_t bOff0 = (uint32_t)((wn * 32 + (sel >> 1) * 8 + (lane & 7)) * ROWB + (sel & 1) * 16);
    uint32_t bOff1 = (uint32_t)((wn * 32 + 16 + (sel >> 1) * 8 + (lane & 7)) * ROWB + (sel & 1) * 16);

    float acc[2][4][4];
#pragma unroll
    for (int i = 0; i < 2; i++)
#pragma unroll
        for (int j = 0; j < 4; j++)
#pragma unroll
            for (int k = 0; k < 4; k++) acc[i][j][k] = 0.f;

    const int NST = D_DIM / BK;  // 32
#pragma unroll
    for (int s = 0; s < 3; s++) {
        if (prod) {
            const char* src = (const char*)gp + s * 64;
            uint32_t d = sdst + s * STAGE;
#pragma unroll
            for (int i = 0; i < 4; i++) cp16(d + 16 * i, src + 16 * i);
        }
        CP_COMMIT();
    }

    for (int kt = 0; kt < NST; kt++) {
        CP_WAIT(2);
        __syncthreads();
        if (kt + 3 < NST && prod) {
            const char* src = (const char*)gp + (kt + 3) * 64;
            uint32_t d = sdst + ((kt + 3) & 3) * STAGE;
#pragma unroll
            for (int i = 0; i < 4; i++) cp16(d + 16 * i, src + 16 * i);
        }
        CP_COMMIT();   // uniform commit keeps wait_group(2) semantics exact
        compute_stage(sbase + (kt & 3) * STAGE, aOff, bOff0, bOff1, acc);
    }

    // epilogue: bias + gelu -> fp16 H
    const float* bcol = b1 + (size_t)e * F_DIM + n0 + wn * 32;
#pragma unroll
    for (int mi = 0; mi < 2; mi++) {
#pragma unroll
        for (int half_ = 0; half_ < 2; half_++) {
            int gr = m0 + wm * 32 + mi * 16 + g + half_ * 8;
            if (gr < rows) {
                __half* hrow = g_Hh + (size_t)(base + gr) * F_DIM + n0 + wn * 32;
#pragma unroll
                for (int nj = 0; nj < 4; nj++) {
                    int n = nj * 8 + q2 * 2;
                    float v0 = acc[mi][nj][half_ * 2 + 0] + bcol[n];
                    float v1 = acc[mi][nj][half_ * 2 + 1] + bcol[n + 1];
                    float g0 = 0.5f * v0 * (1.0f + erff(v0 * 0.7071067811865475f));
                    float g1 = 0.5f * v1 * (1.0f + erff(v1 * 0.7071067811865475f));
                    *(__half2*)(hrow + n) = __floats2half2_rn(g0, g1);
                }
            }
        }
    }
}

// ---------------------------------------------------------------------------
// launch 4: GEMM2: Y = Hh @ W2h^T + b2; out[tok] += w * Y (2-way atomic)
// ---------------------------------------------------------------------------
__global__ __launch_bounds__(256, 3) void gemm2_mma(const float* __restrict__ b2,
                                                    float* __restrict__ out) {
    int e = blockIdx.z;
    int rows = g_counts[e];
    int m0 = blockIdx.y * BM;
    if (m0 >= rows) return;
    int base = g_offsets[e];
    int n0 = blockIdx.x * BN;   // over D_DIM

    extern __shared__ char smem[];
    uint32_t sbase = smem_u32(smem);
    int tid = threadIdx.x;
    int wid = tid >> 5, lane = tid & 31;
    int wm = wid & 1, wn = wid >> 1;
    int g = lane >> 2, q2 = lane & 3;

    bool prod = tid < 192;
    const __half* gp = 0;
    uint32_t sdst = 0;
    if (tid < 64) {
        int ar = m0 + tid; if (ar >= rows) ar = rows - 1;
        gp = g_Hh + (size_t)(base + ar) * F_DIM;
        sdst = sbase + APL + tid * ROWB;
    } else if (tid < 192) {
        int br = tid - 64;
        gp = g_W2h + ((size_t)e * D_DIM + n0 + br) * F_DIM;
        sdst = sbase + BPL + br * ROWB;
    }

    int sel = lane >> 3;
    uint32_t aOff = (uint32_t)((wm * 32 + (lane & 15)) * ROWB + (lane >> 4) * 16);
    uint32_t bOff0 = (uint32_t)((wn * 32 + (sel >> 1) * 8 + (lane & 7)) * ROWB + (sel & 1) * 16);
    uint32_t bOff1 = (uint32_t)((wn * 32 + 16 + (sel >> 1) * 8 + (lane & 7)) * ROWB + (sel & 1) * 16);

    float acc[2][4][4];
#pragma unroll
    for (int i = 0; i < 2; i++)
#pragma unroll
        for (int j = 0; j < 4; j++)
#pragma unroll
            for (int k = 0; k < 4; k++) acc[i][j][k] = 0.f;

    const int NST = F_DIM / BK;  // 128
#pragma unroll
    for (int s = 0; s < 3; s++) {
        if (prod) {
            const char* src = (const char*)gp + s * 64;
            uint32_t d = sdst + s * STAGE;
#pragma unroll
            for (int i = 0; i < 4; i++) cp16(d + 16 * i, src + 16 * i);
        }
        CP_COMMIT();
    }

    for (int kt = 0; kt < NST; kt++) {
        CP_WAIT(2);
        __syncthreads();
        if (kt + 3 < NST && prod) {
            const char* src = (const char*)gp + (kt + 3) * 64;
            uint32_t d = sdst + ((kt + 3) & 3) * STAGE;
#pragma unroll
            for (int i = 0; i < 4; i++) cp16(d + 16 * i, src + 16 * i);
        }
        CP_COMMIT();
        compute_stage(sbase + (kt & 3) * STAGE, aOff, bOff0, bOff1, acc);
    }

    const float* bcol = b2 + (size_t)e * D_DIM + n0 + wn * 32;
#pragma unroll
    for (int mi = 0; mi < 2; mi++) {
#pragma unroll
        for (int half_ = 0; half_ < 2; half_++) {
            int gr = m0 + wm * 32 + mi * 16 + g + half_ * 8;
            if (gr < rows) {
                int tok = g_rowmap[base + gr];
                float w = g_roww[base + gr];
                float* op = out + (size_t)tok * D_DIM + n0 + wn * 32;
#pragma unroll
                for (int nj = 0; nj < 4; nj++) {
                    int n = nj * 8 + q2 * 2;
                    float v0 = acc[mi][nj][half_ * 2 + 0] + bcol[n];
                    float v1 = acc[mi][nj][half_ * 2 + 1] + bcol[n + 1];
                    atomicAdd(&op[n], w * v0);
                    atomicAdd(&op[n + 1], w * v1);
                }
            }
        }
    }
}

// ---------------------------------------------------------------------------
extern "C" void kernel_launch(void* const* d_in, const int* in_sizes, int n_in,
                              void* d_out, int out_size) {
    const float* x  = (const float*)d_in[0];
    const float* Wr = (const float*)d_in[1];
    const float* W1 = (const float*)d_in[2];
    const float* b1 = (const float*)d_in[3];
    const float* W2 = (const float*)d_in[4];
    const float* b2 = (const float*)d_in[5];
    float* out = (float*)d_out;

    cudaFuncSetAttribute(gemm1_mma, cudaFuncAttributeMaxDynamicSharedMemorySize, DSMEM);
    cudaFuncSetAttribute(gemm2_mma, cudaFuncAttributeMaxDynamicSharedMemorySize, DSMEM);

    // launch indices: 0 f2h_zero, 1 router, 2 scanfill, 3 gemm1 (ncu target), 4 gemm2
    f2h_zero_kernel<<<(unsigned)((X_B4 + 2 * W_B4) / 256), 256>>>(x, W1, W2, out);
    router_kernel<<<(T_TOK * 32) / 256, 256>>>(x, Wr);
    scanfill_kernel<<<1, 256>>>();
    gemm1_mma<<<dim3(F_DIM / BN, T_TOK / BM, N_EXP), 256, DSMEM>>>(b1);
    gemm2_mma<<<dim3(D_DIM / BN, T_TOK / BM, N_EXP), 256, DSMEM>>>(b2, out);
}

// round 14
// speedup vs baseline: 1.0602x; 1.0602x over previous
#include <cuda_runtime.h>
#include <cuda_fp16.h>
#include <math.h>
#include <stdint.h>

#define T_TOK 4096
#define D_DIM 1024
#define F_DIM 4096
#define N_EXP 8
#define TOTAL_ROWS (T_TOK * 2)

#define BM 128
#define BN 128
#define BK 32

// smem: A plane 128 rows, B plane 128 rows, 80B row stride (64B data + 16B pad)
#define ROWB 80
#define APL 0
#define BPL (128 * ROWB)            // 10240
#define STAGE (256 * ROWB)          // 20480
#define NBUF 3
#define DSMEM (NBUF * STAGE)        // 61440  (3 CTAs = 184320B <= 228KB)

// ---- scratch (device globals: no allocations allowed) ----
__device__ __half g_Hh[(size_t)TOTAL_ROWS * F_DIM];
__device__ __half g_W1h[(size_t)N_EXP * F_DIM * D_DIM];
__device__ __half g_W2h[(size_t)N_EXP * D_DIM * F_DIM];
__device__ __half g_xh[(size_t)T_TOK * D_DIM];
__device__ int   g_rowmap[TOTAL_ROWS];
__device__ float g_roww[TOTAL_ROWS];
__device__ int   g_counts[N_EXP];
__device__ int   g_offsets[N_EXP];
__device__ int   g_tope[T_TOK * 2];
__device__ float g_topw[T_TOK * 2];

// ---------------- PTX helpers ----------------
__device__ __forceinline__ uint32_t smem_u32(const void* p) {
    uint32_t a;
    asm("{ .reg .u64 t; cvta.to.shared.u64 t, %1; cvt.u32.u64 %0, t; }" : "=r"(a) : "l"(p));
    return a;
}
__device__ __forceinline__ void cp16(uint32_t dst, const void* src) {
    asm volatile("cp.async.cg.shared.global [%0], [%1], 16;" :: "r"(dst), "l"(src));
}
#define CP_COMMIT() asm volatile("cp.async.commit_group;" ::: "memory")
#define CP_WAIT(n)  asm volatile("cp.async.wait_group %0;" :: "n"(n) : "memory")
__device__ __forceinline__ void ldsm4(uint32_t& r0, uint32_t& r1, uint32_t& r2, uint32_t& r3,
                                      uint32_t a) {
    asm volatile("ldmatrix.sync.aligned.m8n8.x4.shared.b16 {%0,%1,%2,%3}, [%4];"
                 : "=r"(r0), "=r"(r1), "=r"(r2), "=r"(r3) : "r"(a));
}
__device__ __forceinline__ void mma16816(float* c, uint32_t a0, uint32_t a1,
                                         uint32_t a2, uint32_t a3,
                                         uint32_t b0, uint32_t b1) {
    asm volatile("mma.sync.aligned.m16n8k16.row.col.f32.f16.f16.f32 "
                 "{%0,%1,%2,%3}, {%4,%5,%6,%7}, {%8,%9}, {%0,%1,%2,%3};"
                 : "+f"(c[0]), "+f"(c[1]), "+f"(c[2]), "+f"(c[3])
                 : "r"(a0), "r"(a1), "r"(a2), "r"(a3), "r"(b0), "r"(b1));
}

// one BK=32 stage, warp tile 64x64: 8 ldsm.x4 per ks for 32 HMMAs (0.25/HMMA)
__device__ __forceinline__ void compute_stage(uint32_t bufb, uint32_t aOff,
                                              uint32_t bOffBase,
                                              float acc[4][8][4]) {
#pragma unroll
    for (int ks = 0; ks < 2; ks++) {
        uint32_t kb = ks * 32;
        uint32_t b0[8], b1[8];
#pragma unroll
        for (int p = 0; p < 4; p++)
            ldsm4(b0[2 * p], b1[2 * p], b0[2 * p + 1], b1[2 * p + 1],
                  bufb + BPL + bOffBase + p * (16 * ROWB) + kb);
#pragma unroll
        for (int mi = 0; mi < 4; mi++) {
            uint32_t a0, a1, a2, a3;
            ldsm4(a0, a1, a2, a3, bufb + APL + aOff + mi * (16 * ROWB) + kb);
#pragma unroll
            for (int nj = 0; nj < 8; nj++)
                mma16816(acc[mi][nj], a0, a1, a2, a3, b0[nj], b1[nj]);
        }
    }
}

// ---------------------------------------------------------------------------
// launch 0: fp32->fp16 converts for x|W1|W2, plus zero(out) and counts reset
#define X_B4   ((size_t)(T_TOK * D_DIM / 4))
#define W_B4   ((size_t)N_EXP * F_DIM * D_DIM / 4)
__global__ void f2h_zero_kernel(const float* __restrict__ x,
                                const float* __restrict__ W1,
                                const float* __restrict__ W2,
                                float* __restrict__ out) {
    size_t i = (size_t)blockIdx.x * blockDim.x + threadIdx.x;
    if (i < X_B4) ((float4*)out)[i] = make_float4(0.f, 0.f, 0.f, 0.f);
    if (i < 8) g_counts[i] = 0;
    const float* s;
    __half* d;
    size_t j = i;
    if (j < X_B4) { s = x; d = g_xh; }
    else if (j < X_B4 + W_B4) { s = W1; d = g_W1h; j -= X_B4; }
    else { s = W2; d = g_W2h; j -= X_B4 + W_B4; }
    float4 v = ((const float4*)s)[j];
    __half2* dp = (__half2*)d;
    dp[2 * j] = __floats2half2_rn(v.x, v.y);
    dp[2 * j + 1] = __floats2half2_rn(v.z, v.w);
}

// launch 1: router
__global__ void router_kernel(const float* __restrict__ x, const float* __restrict__ Wr) {
    int gtid = blockIdx.x * blockDim.x + threadIdx.x;
    int t = gtid >> 5, lane = gtid & 31;
    if (t >= T_TOK) return;
    const float* xr = x + (size_t)t * D_DIM;
    float xv[32];
#pragma unroll
    for (int i = 0; i < 32; i++) xv[i] = xr[lane + i * 32];
    float logit[N_EXP];
#pragma unroll
    for (int e = 0; e < N_EXP; e++) {
        const float* w = Wr + (size_t)e * D_DIM;
        float s = 0.f;
#pragma unroll
        for (int i = 0; i < 32; i++) s += xv[i] * w[lane + i * 32];
#pragma unroll
        for (int o = 16; o > 0; o >>= 1) s += __shfl_xor_sync(0xffffffffu, s, o);
        logit[e] = s;
    }
    if (lane == 0) {
        int i0 = 0; float m0v = logit[0];
#pragma unroll
        for (int e = 1; e < N_EXP; e++) if (logit[e] > m0v) { m0v = logit[e]; i0 = e; }
        int i1 = -1; float m1v = -3.0e38f;
#pragma unroll
        for (int e = 0; e < N_EXP; e++) if (e != i0 && logit[e] > m1v) { m1v = logit[e]; i1 = e; }
        float e1 = expf(m1v - m0v);
        float w0 = 1.f / (1.f + e1);
        float w1 = e1 * w0;
        g_tope[2 * t] = i0;     g_topw[2 * t] = w0;
        g_tope[2 * t + 1] = i1; g_topw[2 * t + 1] = w1;
        atomicAdd(&g_counts[i0], 1);
        atomicAdd(&g_counts[i1], 1);
    }
}

// launch 2: scan + fill merged
__global__ void scanfill_kernel() {
    __shared__ int scur[N_EXP];
    int tid = threadIdx.x;
    if (tid == 0) {
        int o = 0;
        for (int e = 0; e < N_EXP; e++) { g_offsets[e] = o; scur[e] = o; o += g_counts[e]; }
    }
    __syncthreads();
    for (int t = tid; t < T_TOK; t += 256) {
#pragma unroll
        for (int k = 0; k < 2; k++) {
            int e = g_tope[2 * t + k];
            int pos = atomicAdd(&scur[e], 1);
            g_rowmap[pos] = t;
            g_roww[pos] = g_topw[2 * t + k];
        }
    }
}

// ---------------------------------------------------------------------------
// launch 3: GEMM1. 128x128 CTA, 4 warps of 64x64, cp.async 3-buf, ldmatrix
// ---------------------------------------------------------------------------
__global__ __launch_bounds__(128, 3) void gemm1_mma(const float* __restrict__ b1) {
    int e = blockIdx.z;
    int rows = g_counts[e];
    int m0 = blockIdx.y * BM;
    if (m0 >= rows) return;
    int base = g_offsets[e];
    int n0 = blockIdx.x * BN;

    extern __shared__ char smem[];
    uint32_t sbase = smem_u32(smem);
    int tid = threadIdx.x;
    int wid = tid >> 5, lane = tid & 31;
    int wm = wid & 1, wn = wid >> 1;          // 2x2 warp grid, 64x64 tiles
    int g = lane >> 2, q2 = lane & 3;

    // producer: each thread owns A row tid and B row tid (64B each per stage)
    int ar = m0 + tid; if (ar >= rows) ar = rows - 1;
    const __half* gpA = g_xh + (size_t)g_rowmap[base + ar] * D_DIM;
    const __half* gpB = g_W1h + ((size_t)e * F_DIM + n0 + tid) * D_DIM;
    uint32_t sdA = sbase + APL + tid * ROWB;
    uint32_t sdB = sbase + BPL + tid * ROWB;

    int sel = lane >> 3;
    uint32_t aOff = (uint32_t)((wm * 64 + (lane & 15)) * ROWB + (lane >> 4) * 16);
    uint32_t bOffBase = (uint32_t)((wn * 64 + (sel >> 1) * 8 + (lane & 7)) * ROWB + (sel & 1) * 16);

    float acc[4][8][4];
#pragma unroll
    for (int i = 0; i < 4; i++)
#pragma unroll
        for (int j = 0; j < 8; j++)
#pragma unroll
            for (int k = 0; k < 4; k++) acc[i][j][k] = 0.f;

    const int NST = D_DIM / BK;  // 32
#pragma unroll
    for (int s = 0; s < 2; s++) {
        const char* sa = (const char*)gpA + s * 64;
        const char* sb = (const char*)gpB + s * 64;
        uint32_t dA = sdA + s * STAGE, dB = sdB + s * STAGE;
#pragma unroll
        for (int i = 0; i < 4; i++) { cp16(dA + 16 * i, sa + 16 * i); cp16(dB + 16 * i, sb + 16 * i); }
        CP_COMMIT();
    }

    int bufC = 0;
    for (int kt = 0; kt < NST; kt++) {
        CP_WAIT(1);
        __syncthreads();
        if (kt + 2 < NST) {
            int s = kt + 2;
            const char* sa = (const char*)gpA + s * 64;
            const char* sb = (const char*)gpB + s * 64;
            int bw = (bufC + 2 == NBUF) ? 2 : bufC - 1;  // (kt+2) % 3
            bw = (kt + 2) % NBUF;
            uint32_t dA = sdA + bw * STAGE, dB = sdB + bw * STAGE;
#pragma unroll
            for (int i = 0; i < 4; i++) { cp16(dA + 16 * i, sa + 16 * i); cp16(dB + 16 * i, sb + 16 * i); }
        }
        CP_COMMIT();   // uniform commit keeps wait_group(1) semantics exact
        compute_stage(sbase + bufC * STAGE, aOff, bOffBase, acc);
        bufC = (bufC + 1 == NBUF) ? 0 : bufC + 1;
    }

    // epilogue: bias + gelu -> fp16 H (warp covers 64 rows x 64 cols)
    const float* bcol = b1 + (size_t)e * F_DIM + n0 + wn * 64;
#pragma unroll
    for (int mi = 0; mi < 4; mi++) {
#pragma unroll
        for (int half_ = 0; half_ < 2; half_++) {
            int gr = m0 + wm * 64 + mi * 16 + g + half_ * 8;
            if (gr < rows) {
                __half* hrow = g_Hh + (size_t)(base + gr) * F_DIM + n0 + wn * 64;
#pragma unroll
                for (int nj = 0; nj < 8; nj++) {
                    int n = nj * 8 + q2 * 2;
                    float v0 = acc[mi][nj][half_ * 2 + 0] + bcol[n];
                    float v1 = acc[mi][nj][half_ * 2 + 1] + bcol[n + 1];
                    float g0 = 0.5f * v0 * (1.0f + erff(v0 * 0.7071067811865475f));
                    float g1 = 0.5f * v1 * (1.0f + erff(v1 * 0.7071067811865475f));
                    *(__half2*)(hrow + n) = __floats2half2_rn(g0, g1);
                }
            }
        }
    }
}

// ---------------------------------------------------------------------------
// launch 4: GEMM2: out[tok] += w * (Hh @ W2h^T + b2)  (2-way atomic)
// ---------------------------------------------------------------------------
__global__ __launch_bounds__(128, 3) void gemm2_mma(const float* __restrict__ b2,
                                                    float* __restrict__ out) {
    int e = blockIdx.z;
    int rows = g_counts[e];
    int m0 = blockIdx.y * BM;
    if (m0 >= rows) return;
    int base = g_offsets[e];
    int n0 = blockIdx.x * BN;   // over D_DIM

    extern __shared__ char smem[];
    uint32_t sbase = smem_u32(smem);
    int tid = threadIdx.x;
    int wid = tid >> 5, lane = tid & 31;
    int wm = wid & 1, wn = wid >> 1;
    int g = lane >> 2, q2 = lane & 3;

    int ar = m0 + tid; if (ar >= rows) ar = rows - 1;
    const __half* gpA = g_Hh + (size_t)(base + ar) * F_DIM;
    const __half* gpB = g_W2h + ((size_t)e * D_DIM + n0 + tid) * F_DIM;
    uint32_t sdA = sbase + APL + tid * ROWB;
    uint32_t sdB = sbase + BPL + tid * ROWB;

    int sel = lane >> 3;
    uint32_t aOff = (uint32_t)((wm * 64 + (lane & 15)) * ROWB + (lane >> 4) * 16);
    uint32_t bOffBase = (uint32_t)((wn * 64 + (sel >> 1) * 8 + (lane & 7)) * ROWB + (sel & 1) * 16);

    float acc[4][8][4];
#pragma unroll
    for (int i = 0; i < 4; i++)
#pragma unroll
        for (int j = 0; j < 8; j++)
#pragma unroll
            for (int k = 0; k < 4; k++) acc[i][j][k] = 0.f;

    const int NST = F_DIM / BK;  // 128
#pragma unroll
    for (int s = 0; s < 2; s++) {
        const char* sa = (const char*)gpA + s * 64;
        const char* sb = (const char*)gpB + s * 64;
        uint32_t dA = sdA + s * STAGE, dB = sdB + s * STAGE;
#pragma unroll
        for (int i = 0; i < 4; i++) { cp16(dA + 16 * i, sa + 16 * i); cp16(dB + 16 * i, sb + 16 * i); }
        CP_COMMIT();
    }

    int bufC = 0;
    for (int kt = 0; kt < NST; kt++) {
        CP_WAIT(1);
        __syncthreads();
        if (kt + 2 < NST) {
            int s = kt + 2;
            const char* sa = (const char*)gpA + s * 64;
            const char* sb = (const char*)gpB + s * 64;
            int bw = (kt + 2) % NBUF;
            uint32_t dA = sdA + bw * STAGE, dB = sdB + bw * STAGE;
#pragma unroll
            for (int i = 0; i < 4; i++) { cp16(dA + 16 * i, sa + 16 * i); cp16(dB + 16 * i, sb + 16 * i); }
        }
        CP_COMMIT();
        compute_stage(sbase + bufC * STAGE, aOff, bOffBase, acc);
        bufC = (bufC + 1 == NBUF) ? 0 : bufC + 1;
    }

    const float* bcol = b2 + (size_t)e * D_DIM + n0 + wn * 64;
#pragma unroll
    for (int mi = 0; mi < 4; mi++) {
#pragma unroll
        for (int half_ = 0; half_ < 2; half_++) {
            int gr = m0 + wm * 64 + mi * 16 + g + half_ * 8;
            if (gr < rows) {
                int tok = g_rowmap[base + gr];
                float w = g_roww[base + gr];
                float* op = out + (size_t)tok * D_DIM + n0 + wn * 64;
#pragma unroll
                for (int nj = 0; nj < 8; nj++) {
                    int n = nj * 8 + q2 * 2;
                    float v0 = acc[mi][nj][half_ * 2 + 0] + bcol[n];
                    float v1 = acc[mi][nj][half_ * 2 + 1] + bcol[n + 1];
                    atomicAdd(&op[n], w * v0);
                    atomicAdd(&op[n + 1], w * v1);
                }
            }
        }
    }
}

// ---------------------------------------------------------------------------
extern "C" void kernel_launch(void* const* d_in, const int* in_sizes, int n_in,
                              void* d_out, int out_size) {
    const float* x  = (const float*)d_in[0];
    const float* Wr = (const float*)d_in[1];
    const float* W1 = (const float*)d_in[2];
    const float* b1 = (const float*)d_in[3];
    const float* W2 = (const float*)d_in[4];
    const float* b2 = (const float*)d_in[5];
    float* out = (float*)d_out;

    cudaFuncSetAttribute(gemm1_mma, cudaFuncAttributeMaxDynamicSharedMemorySize, DSMEM);
    cudaFuncSetAttribute(gemm2_mma, cudaFuncAttributeMaxDynamicSharedMemorySize, DSMEM);

    // launch indices: 0 f2h_zero, 1 router, 2 scanfill, 3 gemm1 (ncu target), 4 gemm2
    f2h_zero_kernel<<<(unsigned)((X_B4 + 2 * W_B4) / 256), 256>>>(x, W1, W2, out);
    router_kernel<<<(T_TOK * 32) / 256, 256>>>(x, Wr);
    scanfill_kernel<<<1, 256>>>();
    gemm1_mma<<<dim3(F_DIM / BN, T_TOK / BM, N_EXP), 128, DSMEM>>>(b1);
    gemm2_mma<<<dim3(D_DIM / BN, T_TOK / BM, N_EXP), 128, DSMEM>>>(b2, out);
}